// round 14
// baseline (speedup 1.0000x reference)
#include <cuda_runtime.h>
#include <cuda_bf16.h>
#include <cuda_fp16.h>

// Problem constants (fixed shapes for BevPoolV2_8478265442577)
#define B_     1
#define N_CAM  6
#define D_BINS 118
#define HF     32
#define WF     88
#define C_     80
#define DZ     1
#define DY     128
#define DX     128

#define N_DEPTH (B_ * N_CAM * D_BINS * HF * WF)   // 1,993,728
#define N_FEAT  (B_ * N_CAM * HF * WF * C_)       // 1,351,680
#define N_PTS   1000000
#define S_      (DZ * DY * DX)                    // 16,384
#define N_OUT4  (B_ * C_ * S_ / 4)                // 327,680 float4 in output
#define N_FEAT4 (N_FEAT / 4)                      // 337,920 float4 in feat

// fp16 mirror of feat: 80 halves per row = 160 B per row (10 x uint4)
__device__ __align__(16) static __half g_feat16[N_FEAT];

// ---------------------------------------------------------------------------
// Fused preamble: zero the output AND build the fp16 feat mirror.
// ---------------------------------------------------------------------------
__global__ void __launch_bounds__(256)
prep_kernel(float4* __restrict__ out, const float4* __restrict__ src) {
    const int tid    = blockIdx.x * blockDim.x + threadIdx.x;
    const int stride = gridDim.x * blockDim.x;
    uint2* __restrict__ dst = (uint2*)g_feat16;

    for (int i = tid; i < N_OUT4; i += stride)
        out[i] = make_float4(0.f, 0.f, 0.f, 0.f);

    for (int i = tid; i < N_FEAT4; i += stride) {
        float4 v = src[i];
        __half2 h0 = __floats2half2_rn(v.x, v.y);
        __half2 h1 = __floats2half2_rn(v.z, v.w);
        uint2 u;
        u.x = *reinterpret_cast<unsigned int*>(&h0);
        u.y = *reinterpret_cast<unsigned int*>(&h1);
        dst[i] = u;
    }
}

// half2 (as uint) -> float2
__device__ __forceinline__ float2 h2f(unsigned int h) {
    return __half22float2(*reinterpret_cast<const __half2*>(&h));
}

// ---------------------------------------------------------------------------
// One warp per interval, THREE points per iteration, TWO iterations per
// unrolled body (both feat LDG.128s issued back-to-back -> MLP 2).
// Lane groups: {0-9}, {10-19}, {20-29} each own a full 80-ch feat row as
// 10 x uint4 (8 fp16 channels per lane). Lanes 30-31 shadow group 2.
// Per 30-point chunk: 3 scalar LDGs (rd, rf, depth gather) by lanes 0-29.
// Cross-group shuffle reduction per interval merges the 3 partial sums.
// Intervals are disjoint BEV bins -> plain stores, no atomics.
// ---------------------------------------------------------------------------
__global__ void __launch_bounds__(256)
bev_pool_kernel(const float* __restrict__ depth,
                const int*   __restrict__ ranks_depth,
                const int*   __restrict__ ranks_feat,
                const int*   __restrict__ ranks_bev,
                const int*   __restrict__ istart,
                const int*   __restrict__ ilen,
                int n_intervals,
                float* __restrict__ out) {
    const int gwarp = (blockIdx.x * blockDim.x + threadIdx.x) >> 5;
    const int lane  = threadIdx.x & 31;
    if (gwarp >= n_intervals) return;

    const int start = istart[gwarp];
    const int len   = ilen[gwarp];

    // group id (0,1,2) and lane-within-group (0..9); lanes 30,31 shadow grp 2
    const int grp = (lane >= 30) ? 2 : (lane / 10);
    const int fl  = (lane >= 30) ? (lane - 30) : (lane - grp * 10);

    const uint4* __restrict__ fbase = (const uint4*)g_feat16;  // row = 10 uint4

    // 8 channel accumulators (channels fl*8 .. fl*8+7)
    float2 a0 = make_float2(0.f, 0.f);
    float2 a1 = make_float2(0.f, 0.f);
    float2 a2 = make_float2(0.f, 0.f);
    float2 a3 = make_float2(0.f, 0.f);

    for (int base = 0; base < len; base += 30) {
        // ---- chunk scalars: lanes 0-29 load (rd, rf) and gather depth ----
        const int off = base + lane;
        float dv  = 0.f;
        int   rfv = 0;
        if (lane < 30 && off < len) {
            const int p = start + off;
            int rd = __ldg(&ranks_depth[p]);
            rfv    = __ldg(&ranks_feat[p]);
            dv     = __ldg(&depth[rd]);
        }

        #pragma unroll
        for (int j = 0; j < 30; j += 6) {
            // two iterations' scalars (independent)
            const int sA = j + grp;
            const int sB = j + 3 + grp;
            const float dA  = __shfl_sync(0xffffffffu, dv,  sA);
            const int   rfA = __shfl_sync(0xffffffffu, rfv, sA);
            const float dB  = __shfl_sync(0xffffffffu, dv,  sB);
            const int   rfB = __shfl_sync(0xffffffffu, rfv, sB);

            // two independent 128-bit gathers in flight
            const uint4 uA = __ldg(fbase + (size_t)rfA * 10 + fl);
            const uint4 uB = __ldg(fbase + (size_t)rfB * 10 + fl);

            {
                const float2 f0 = h2f(uA.x);
                const float2 f1 = h2f(uA.y);
                const float2 f2 = h2f(uA.z);
                const float2 f3 = h2f(uA.w);
                a0.x = fmaf(dA, f0.x, a0.x);
                a0.y = fmaf(dA, f0.y, a0.y);
                a1.x = fmaf(dA, f1.x, a1.x);
                a1.y = fmaf(dA, f1.y, a1.y);
                a2.x = fmaf(dA, f2.x, a2.x);
                a2.y = fmaf(dA, f2.y, a2.y);
                a3.x = fmaf(dA, f3.x, a3.x);
                a3.y = fmaf(dA, f3.y, a3.y);
            }
            {
                const float2 f0 = h2f(uB.x);
                const float2 f1 = h2f(uB.y);
                const float2 f2 = h2f(uB.z);
                const float2 f3 = h2f(uB.w);
                a0.x = fmaf(dB, f0.x, a0.x);
                a0.y = fmaf(dB, f0.y, a0.y);
                a1.x = fmaf(dB, f1.x, a1.x);
                a1.y = fmaf(dB, f1.y, a1.y);
                a2.x = fmaf(dB, f2.x, a2.x);
                a2.y = fmaf(dB, f2.y, a2.y);
                a3.x = fmaf(dB, f3.x, a3.x);
                a3.y = fmaf(dB, f3.y, a3.y);
            }
        }
    }

    // ---- merge the 3 group partials into lanes 0-9 ----
    float v[8] = {a0.x, a0.y, a1.x, a1.y, a2.x, a2.y, a3.x, a3.y};
    #pragma unroll
    for (int k = 0; k < 8; k++) {
        float t1 = __shfl_sync(0xffffffffu, v[k], lane + 10);
        float t2 = __shfl_sync(0xffffffffu, v[k], lane + 20);
        v[k] += t1 + t2;      // valid for lanes 0-9
    }

    // ---- store: output layout (B, C, Dz, Dy, Dx); bev = b*S + s ----
    if (lane < 10) {
        int bev = __ldg(&ranks_bev[start]);
        int b   = bev / S_;
        int s   = bev - b * S_;
        float* o = out + (size_t)b * C_ * S_ + s;
        const int c = lane * 8;
        #pragma unroll
        for (int k = 0; k < 8; k++)
            o[(size_t)(c + k) * S_] = v[k];
    }
}

// ---------------------------------------------------------------------------
extern "C" void kernel_launch(void* const* d_in, const int* in_sizes, int n_in,
                              void* d_out, int out_size) {
    const float* depth = nullptr;
    const float* feat  = nullptr;
    const int*   ranks[3] = {nullptr, nullptr, nullptr};
    int nrk = 0;
    const int* small_arr[2] = {nullptr, nullptr};
    int small_sz[2] = {0, 0};
    int nsmall = 0;

    for (int i = 0; i < n_in; i++) {
        int sz = in_sizes[i];
        if (sz == N_DEPTH && !depth) {
            depth = (const float*)d_in[i];
        } else if (sz == N_FEAT && !feat) {
            feat = (const float*)d_in[i];
        } else if (sz == N_PTS && nrk < 3) {
            ranks[nrk++] = (const int*)d_in[i];   // order: depths, feats, bevs
        } else if (sz == 5) {
            // bev_feat_shape metadata — compile-time constants here
        } else if (nsmall < 2) {
            small_arr[nsmall] = (const int*)d_in[i];  // order: starts, lengths
            small_sz[nsmall] = sz;
            nsmall++;
        }
    }

    const int* istart = small_arr[0];
    const int* ilen   = small_arr[1];
    int n_intervals   = small_sz[0];

    float* out = (float*)d_out;

    // 1) fused preamble: zero output + build fp16 feat mirror (full-chip wave)
    prep_kernel<<<2048, 256>>>((float4*)out, (const float4*)feat);

    // 2) pooled gather-multiply-store, one warp per interval, 3 pts/iter,
    //    2 iters per unrolled body (MLP 2)
    const int threads = 256;                    // 8 warps per block
    int blocks = (n_intervals + 7) / 8;
    if (blocks < 1) blocks = 1;
    bev_pool_kernel<<<blocks, threads>>>(depth,
                                         ranks[0], ranks[1], ranks[2],
                                         istart, ilen, n_intervals, out);
}

// round 15
// speedup vs baseline: 1.6639x; 1.6639x over previous
#include <cuda_runtime.h>
#include <cuda_bf16.h>
#include <cuda_fp16.h>

// Problem constants (fixed shapes for BevPoolV2_8478265442577)
#define B_     1
#define N_CAM  6
#define D_BINS 118
#define HF     32
#define WF     88
#define C_     80
#define DZ     1
#define DY     128
#define DX     128

#define N_DEPTH (B_ * N_CAM * D_BINS * HF * WF)   // 1,993,728
#define N_FEAT  (B_ * N_CAM * HF * WF * C_)       // 1,351,680
#define N_PTS   1000000
#define S_      (DZ * DY * DX)                    // 16,384
#define N_OUT4  (B_ * C_ * S_ / 4)                // 327,680 float4 in output
#define N_FEAT4 (N_FEAT / 4)                      // 337,920 float4 in feat

// fp16 mirror of feat: 80 halves per row = 160 B per row (10 x uint4)
__device__ __align__(16) static __half g_feat16[N_FEAT];

// ---------------------------------------------------------------------------
// Fused preamble: zero the output AND build the fp16 feat mirror.
// ---------------------------------------------------------------------------
__global__ void __launch_bounds__(256)
prep_kernel(float4* __restrict__ out, const float4* __restrict__ src) {
    const int tid    = blockIdx.x * blockDim.x + threadIdx.x;
    const int stride = gridDim.x * blockDim.x;
    uint2* __restrict__ dst = (uint2*)g_feat16;

    for (int i = tid; i < N_OUT4; i += stride)
        out[i] = make_float4(0.f, 0.f, 0.f, 0.f);

    for (int i = tid; i < N_FEAT4; i += stride) {
        float4 v = src[i];
        __half2 h0 = __floats2half2_rn(v.x, v.y);
        __half2 h1 = __floats2half2_rn(v.z, v.w);
        uint2 u;
        u.x = *reinterpret_cast<unsigned int*>(&h0);
        u.y = *reinterpret_cast<unsigned int*>(&h1);
        dst[i] = u;
    }
}

// half2 (as uint) -> float2
__device__ __forceinline__ float2 h2f(unsigned int h) {
    return __half22float2(*reinterpret_cast<const __half2*>(&h));
}

// ---------------------------------------------------------------------------
// One warp per interval, THREE points per inner iteration.
// Lane groups: {0-9}, {10-19}, {20-29} each own a full 80-ch feat row as
// 10 x uint4 (8 fp16 channels per lane). Lanes 30-31 shadow group 2.
// Per 30-point chunk: 3 scalar LDGs (rd, rf, depth gather) by lanes 0-29.
// Per inner iter (3 points): 2 SHFL (per-lane src) + 1 LDG.128 + cvts + 8 FMA.
// Cross-group shuffle reduction per interval merges the 3 partial sums.
// Intervals are disjoint BEV bins -> plain stores, no atomics.
// Loop body identical to the round-11 winner; only block size changed
// (256 -> 128) for finer occupancy quantization (11 blocks/SM = 44 warps).
// ---------------------------------------------------------------------------
__global__ void __launch_bounds__(128)
bev_pool_kernel(const float* __restrict__ depth,
                const int*   __restrict__ ranks_depth,
                const int*   __restrict__ ranks_feat,
                const int*   __restrict__ ranks_bev,
                const int*   __restrict__ istart,
                const int*   __restrict__ ilen,
                int n_intervals,
                float* __restrict__ out) {
    const int gwarp = (blockIdx.x * blockDim.x + threadIdx.x) >> 5;
    const int lane  = threadIdx.x & 31;
    if (gwarp >= n_intervals) return;

    const int start = istart[gwarp];
    const int len   = ilen[gwarp];

    // group id (0,1,2) and lane-within-group (0..9); lanes 30,31 shadow grp 2
    const int grp = (lane >= 30) ? 2 : (lane / 10);
    const int fl  = (lane >= 30) ? (lane - 30) : (lane - grp * 10);

    const uint4* __restrict__ fbase = (const uint4*)g_feat16;  // row = 10 uint4

    // 8 channel accumulators (channels fl*8 .. fl*8+7)
    float2 a0 = make_float2(0.f, 0.f);
    float2 a1 = make_float2(0.f, 0.f);
    float2 a2 = make_float2(0.f, 0.f);
    float2 a3 = make_float2(0.f, 0.f);

    for (int base = 0; base < len; base += 30) {
        // ---- chunk scalars: lanes 0-29 load (rd, rf) and gather depth ----
        const int off = base + lane;
        float dv  = 0.f;
        int   rfv = 0;
        if (lane < 30 && off < len) {
            const int p = start + off;
            int rd = __ldg(&ranks_depth[p]);
            rfv    = __ldg(&ranks_feat[p]);
            dv     = __ldg(&depth[rd]);
        }

        #pragma unroll
        for (int j = 0; j < 30; j += 3) {
            const int src = j + grp;                       // per-lane source
            const float d  = __shfl_sync(0xffffffffu, dv,  src);
            const int   rf = __shfl_sync(0xffffffffu, rfv, src);
            const uint4 u = __ldg(fbase + (size_t)rf * 10 + fl);
            const float2 f0 = h2f(u.x);
            const float2 f1 = h2f(u.y);
            const float2 f2 = h2f(u.z);
            const float2 f3 = h2f(u.w);
            a0.x = fmaf(d, f0.x, a0.x);
            a0.y = fmaf(d, f0.y, a0.y);
            a1.x = fmaf(d, f1.x, a1.x);
            a1.y = fmaf(d, f1.y, a1.y);
            a2.x = fmaf(d, f2.x, a2.x);
            a2.y = fmaf(d, f2.y, a2.y);
            a3.x = fmaf(d, f3.x, a3.x);
            a3.y = fmaf(d, f3.y, a3.y);
        }
    }

    // ---- merge the 3 group partials into lanes 0-9 ----
    float v[8] = {a0.x, a0.y, a1.x, a1.y, a2.x, a2.y, a3.x, a3.y};
    #pragma unroll
    for (int k = 0; k < 8; k++) {
        float t1 = __shfl_sync(0xffffffffu, v[k], lane + 10);
        float t2 = __shfl_sync(0xffffffffu, v[k], lane + 20);
        v[k] += t1 + t2;      // valid for lanes 0-9
    }

    // ---- store: output layout (B, C, Dz, Dy, Dx); bev = b*S + s ----
    if (lane < 10) {
        int bev = __ldg(&ranks_bev[start]);
        int b   = bev / S_;
        int s   = bev - b * S_;
        float* o = out + (size_t)b * C_ * S_ + s;
        const int c = lane * 8;
        #pragma unroll
        for (int k = 0; k < 8; k++)
            o[(size_t)(c + k) * S_] = v[k];
    }
}

// ---------------------------------------------------------------------------
extern "C" void kernel_launch(void* const* d_in, const int* in_sizes, int n_in,
                              void* d_out, int out_size) {
    const float* depth = nullptr;
    const float* feat  = nullptr;
    const int*   ranks[3] = {nullptr, nullptr, nullptr};
    int nrk = 0;
    const int* small_arr[2] = {nullptr, nullptr};
    int small_sz[2] = {0, 0};
    int nsmall = 0;

    for (int i = 0; i < n_in; i++) {
        int sz = in_sizes[i];
        if (sz == N_DEPTH && !depth) {
            depth = (const float*)d_in[i];
        } else if (sz == N_FEAT && !feat) {
            feat = (const float*)d_in[i];
        } else if (sz == N_PTS && nrk < 3) {
            ranks[nrk++] = (const int*)d_in[i];   // order: depths, feats, bevs
        } else if (sz == 5) {
            // bev_feat_shape metadata — compile-time constants here
        } else if (nsmall < 2) {
            small_arr[nsmall] = (const int*)d_in[i];  // order: starts, lengths
            small_sz[nsmall] = sz;
            nsmall++;
        }
    }

    const int* istart = small_arr[0];
    const int* ilen   = small_arr[1];
    int n_intervals   = small_sz[0];

    float* out = (float*)d_out;

    // 1) fused preamble: zero output + build fp16 feat mirror (full-chip wave)
    prep_kernel<<<2048, 256>>>((float4*)out, (const float4*)feat);

    // 2) pooled gather-multiply-store, one warp per interval, 3 pts/iter
    const int threads = 128;                    // 4 warps per block
    int blocks = (n_intervals + 3) / 4;
    if (blocks < 1) blocks = 1;
    bev_pool_kernel<<<blocks, threads>>>(depth,
                                         ranks[0], ranks[1], ranks[2],
                                         istart, ilen, n_intervals, out);
}